// round 12
// baseline (speedup 1.0000x reference)
#include <cuda_runtime.h>
#include <cuda_fp16.h>
#include <cstddef>
#include <cstdint>

typedef unsigned int u32;
typedef unsigned long long ull;

#define NROWS 65536
#define F1 48
#define F2 24
#define F3 10
#define KDIM 784
#define EPSBN 1e-5f

// ----------------------------- device scratch -----------------------------
__device__ float g_Y1[(size_t)NROWS * F1];
__device__ float g_Y2[(size_t)NROWS * F2];
__device__ float g_N1[(size_t)NROWS * F1];   // raw normals, layer 1
__device__ float g_N2[(size_t)NROWS * F2];   // raw normals, layer 2
__device__ uint4 g_w1p[F1 * 49 * 4];         // packed split-fp16 w1 fragments
__device__ float g_p1s[F1 * 512];
__device__ float g_p1q[F1 * 512];
__device__ float g_p2s[F2 * 512];
__device__ float g_p2q[F2 * 512];
__device__ float g_scale1[F1], g_shift1[F1];
__device__ float g_scale2[F2], g_shift2[F2];
__device__ float g_na1, g_nm1, g_na2, g_nm2;
__device__ u32   g_cnt1 = 0, g_cnt2 = 0;

// ----------------------------- helpers ------------------------------------
__device__ __forceinline__ u32 pk2(float a, float b) {
    u32 h;
    asm("cvt.rn.f16x2.f32 %0, %1, %2;" : "=r"(h) : "f"(b), "f"(a));
    return h;
}
__device__ __forceinline__ void split2(float a, float b, u32 &hi, u32 &lo) {
    asm("cvt.rn.f16x2.f32 %0, %1, %2;" : "=r"(hi) : "f"(b), "f"(a));
    float f0, f1;
    asm("{.reg .f16 x,y; mov.b32 {x,y}, %2; cvt.f32.f16 %0, x; cvt.f32.f16 %1, y;}"
        : "=f"(f0), "=f"(f1) : "r"(hi));
    asm("cvt.rn.f16x2.f32 %0, %1, %2;" : "=r"(lo) : "f"(b - f1), "f"(a - f0));
}

#define MMA_F16(c, a, b0v, b1v) \
    asm volatile("mma.sync.aligned.m16n8k16.row.col.f32.f16.f16.f32 " \
        "{%0,%1,%2,%3}, {%4,%5,%6,%7}, {%8,%9}, {%0,%1,%2,%3};" \
        : "+f"((c)[0]), "+f"((c)[1]), "+f"((c)[2]), "+f"((c)[3]) \
        : "r"((a)[0]), "r"((a)[1]), "r"((a)[2]), "r"((a)[3]), \
          "r"(b0v), "r"(b1v))

// ----------------------------- PRNG ----------------------------------------
__device__ __forceinline__ void tf2x32(u32 k0, u32 k1, u32 x0, u32 x1,
                                       u32 &o0, u32 &o1) {
    u32 k2 = k0 ^ k1 ^ 0x1BD11BDAu;
    x0 += k0; x1 += k1;
#define TF_R(r) { x0 += x1; x1 = __funnelshift_l(x1, x1, (r)); x1 ^= x0; }
    TF_R(13) TF_R(15) TF_R(26) TF_R(6)   x0 += k1; x1 += k2 + 1u;
    TF_R(17) TF_R(29) TF_R(16) TF_R(24)  x0 += k2; x1 += k0 + 2u;
    TF_R(13) TF_R(15) TF_R(26) TF_R(6)   x0 += k0; x1 += k1 + 3u;
    TF_R(17) TF_R(29) TF_R(16) TF_R(24)  x0 += k1; x1 += k2 + 4u;
    TF_R(13) TF_R(15) TF_R(26) TF_R(6)   x0 += k2; x1 += k0 + 5u;
#undef TF_R
    o0 = x0; o1 = x1;
}

__device__ __forceinline__ float jax_normal(u32 bits) {
    float u01 = __uint_as_float((bits >> 9) | 0x3f800000u) - 1.0f;
    float u   = fmaxf(-0.99999994f, fmaf(u01, 2.0f, -0.99999994f));
    float w   = -log1pf(-u * u);
    float p;
    if (w < 5.0f) {
        w -= 2.5f;
        p = 2.81022636e-08f;
        p = fmaf(p, w, 3.43273939e-07f);
        p = fmaf(p, w, -3.5233877e-06f);
        p = fmaf(p, w, -4.39150654e-06f);
        p = fmaf(p, w, 0.00021858087f);
        p = fmaf(p, w, -0.00125372503f);
        p = fmaf(p, w, -0.00417768164f);
        p = fmaf(p, w, 0.246640727f);
        p = fmaf(p, w, 1.50140941f);
    } else {
        w = sqrtf(w) - 3.0f;
        p = -0.000200214257f;
        p = fmaf(p, w, 0.000100950558f);
        p = fmaf(p, w, 0.00134934322f);
        p = fmaf(p, w, -0.00367342844f);
        p = fmaf(p, w, 0.00573950773f);
        p = fmaf(p, w, -0.0076224613f);
        p = fmaf(p, w, 0.00943887047f);
        p = fmaf(p, w, 1.00167406f);
        p = fmaf(p, w, 2.83297682f);
    }
    return 1.41421356f * (p * u);
}

// ----------------------------- K0: pack w1 fragments (k-permuted) ---------
__global__ void __launch_bounds__(128) k0_pack(const float* __restrict__ w1) {
    int e = blockIdx.x * 128 + threadIdx.x;
    if (e >= F1 * 49 * 4) return;
    int t = e & 3;
    int ks = (e >> 2) % 49;
    int r = e / 196;
    float4 v = *(const float4*)(w1 + (size_t)r * KDIM + ks * 16 + t * 4);
    u32 h0, l0, h1, l1;
    split2(v.x, v.y, h0, l0);
    split2(v.z, v.w, h1, l1);
    g_w1p[e] = make_uint4(h0, h1, l0, l1);
}

// ----------------------------- K1: streaming HMMA GEMM + N1 gen -----------
// Y1 = x @ w1^T + b1; also generates layer-1 raw normals in stall shadows.
__global__ void __launch_bounds__(128, 4)
k1_mma(const float* __restrict__ x, const float* __restrict__ b1,
       const float* __restrict__ gamma, const float* __restrict__ beta) {
    __shared__ float ys[128 * 49];
    __shared__ float bsm[F1];
    int tid = threadIdx.x;
    int lane = tid & 31, wrp = tid >> 5;
    int g = lane >> 2, t = lane & 3;
    int rowBase = blockIdx.x * 128;

    if (tid < F1) bsm[tid] = b1[tid];

    // constant-foldable noise key: kn = threefry(key(1234)) counter (0,1)
    u32 kn0, kn1;
    tf2x32(0u, 1234u, 0u, 1u, kn0, kn1);
    u32 nbase = (u32)(rowBase + tid) * 48u;

    const float* xA = x + (size_t)(rowBase + wrp * 32 + g) * KDIM + t * 4;
    const uint4* wp = g_w1p + g * 196 + t;    // + nt*1568 + ks*4

    float C[2][6][4];
#pragma unroll
    for (int mt = 0; mt < 2; mt++)
#pragma unroll
        for (int nt = 0; nt < 6; nt++)
#pragma unroll
            for (int e = 0; e < 4; e++) C[mt][nt][e] = 0.f;

    float4 e0, e1, e2, e3, o0, o1, o2, o3;   // even/odd prefetch buffers
#define LDA(ks, v0, v1, v2, v3) { \
    const float* p_ = xA + (ks) * 16; \
    v0 = __ldcs((const float4*)p_); \
    v1 = __ldcs((const float4*)(p_ + 8 * KDIM)); \
    v2 = __ldcs((const float4*)(p_ + 16 * KDIM)); \
    v3 = __ldcs((const float4*)(p_ + 24 * KDIM)); }

#define CVT(v0, v1, v2, v3, a0, a1) { \
    a0[0] = pk2(v0.x, v0.y); a0[1] = pk2(v1.x, v1.y); \
    a0[2] = pk2(v0.z, v0.w); a0[3] = pk2(v1.z, v1.w); \
    a1[0] = pk2(v2.x, v2.y); a1[1] = pk2(v3.x, v3.y); \
    a1[2] = pk2(v2.z, v2.w); a1[3] = pk2(v3.z, v3.w); }

#define MMASTEP(ks, a0, a1) { \
    _Pragma("unroll") \
    for (int nt = 0; nt < 6; nt++) { \
        uint4 w = __ldg(wp + nt * 1568 + (ks) * 4); \
        MMA_F16(C[0][nt], a0, w.x, w.y); \
        MMA_F16(C[1][nt], a1, w.x, w.y); \
        MMA_F16(C[0][nt], a0, w.z, w.w); \
        MMA_F16(C[1][nt], a1, w.z, w.w); } }

#define NOISE(c) { \
    u32 q0_, q1_; \
    tf2x32(kn0, kn1, 0u, nbase + (u32)(c), q0_, q1_); \
    ys[tid * 49 + (c)] = jax_normal(q0_ ^ q1_); }

    LDA(0, e0, e1, e2, e3)
    LDA(1, o0, o1, o2, o3)

#pragma unroll 1
    for (int ks = 0; ks < 48; ks += 2) {
        u32 a0[4], a1[4];
        CVT(e0, e1, e2, e3, a0, a1)
        LDA(ks + 2, e0, e1, e2, e3)
        MMASTEP(ks, a0, a1)
        NOISE(ks)
        CVT(o0, o1, o2, o3, a0, a1)
        if (ks + 3 < 49) { LDA(ks + 3, o0, o1, o2, o3) }
        MMASTEP(ks + 1, a0, a1)
        NOISE(ks + 1)
    }
    {   // ks = 48 (uses even buffer); no noise (only 48 cols)
        u32 a0[4], a1[4];
        CVT(e0, e1, e2, e3, a0, a1)
        MMASTEP(48, a0, a1)
    }
#undef LDA
#undef CVT
#undef MMASTEP
#undef NOISE

    // ---- write N1 (coalesced, from ys staging) ----
    __syncthreads();
    {
        float* ng = g_N1 + (size_t)rowBase * F1;
#pragma unroll 4
        for (int p = 0; p < 48; p++) {
            int i = p * 128 + tid;
            int r = i / F1, cc = i - r * F1;
            ng[i] = ys[r * 49 + cc];
        }
    }
    __syncthreads();

    // ---- epilogue: bias, stage, stats, coalesced write ----
    int rg = lane >> 2, cg = (lane & 3) * 2;
#pragma unroll
    for (int mt = 0; mt < 2; mt++) {
        int r0 = wrp * 32 + mt * 16 + rg;
#pragma unroll
        for (int nt = 0; nt < 6; nt++) {
            int col = nt * 8 + cg;
            ys[r0 * 49 + col]           = C[mt][nt][0] + bsm[col];
            ys[r0 * 49 + col + 1]       = C[mt][nt][1] + bsm[col + 1];
            ys[(r0 + 8) * 49 + col]     = C[mt][nt][2] + bsm[col];
            ys[(r0 + 8) * 49 + col + 1] = C[mt][nt][3] + bsm[col + 1];
        }
    }
    __syncthreads();

    if (tid < F1) {                          // transposed partials [col][block]
        float s = 0.f, q = 0.f;
        for (int r = 0; r < 128; r++) {
            float v = ys[r * 49 + tid];
            s += v; q += v * v;
        }
        g_p1s[tid * 512 + blockIdx.x] = s;
        g_p1q[tid * 512 + blockIdx.x] = q;
    }
    float* yg = g_Y1 + (size_t)rowBase * F1;
#pragma unroll 4
    for (int p = 0; p < 48; p++) {
        int i = p * 128 + tid;
        int r = i / F1, cc = i - r * F1;
        yg[i] = ys[r * 49 + cc];
    }

    // ---- last-block finalize (layer-1 stats + noise consts) ----
    __shared__ u32 fin_last;
    __shared__ float fin_term[F1], fin_beta[F1];
    __threadfence();
    __syncthreads();
    if (tid == 0) fin_last = (atomicAdd(&g_cnt1, 1u) == 511u) ? 1u : 0u;
    __syncthreads();
    if (fin_last == 0u) return;
    __threadfence();

    if (tid < F1) {
        const float4* ps = (const float4*)(g_p1s + (size_t)tid * 512);
        const float4* pq = (const float4*)(g_p1q + (size_t)tid * 512);
        float s = 0.f, q = 0.f;
#pragma unroll 8
        for (int i = 0; i < 128; i++) {
            float4 a = ps[i]; s += (a.x + a.y) + (a.z + a.w);
            float4 b = pq[i]; q += (b.x + b.y) + (b.z + b.w);
        }
        float m = s / 65536.0f;
        float v = fmaxf(q / 65536.0f - m * m, 0.f);
        float ga = gamma[tid], be = beta[tid];
        float sc = ga * rsqrtf(v + EPSBN);
        g_scale1[tid] = sc;
        g_shift1[tid] = be - m * sc;
        fin_beta[tid] = be;
        fin_term[tid] = ga * ga * (v / (v + EPSBN));
    }
    __syncthreads();
    if (tid == 0) {
        float nb = 0.f;
        for (int c = 0; c < F1; c++) nb += fin_beta[c];
        float nm = nb / (float)F1;
        float S = 0.f;
        for (int c = 0; c < F1; c++) {
            float d = fin_beta[c] - nm;
            S += fin_term[c] + d * d;
        }
        float var = (65536.0f * S) / (65536.0f * (float)F1 - 1.0f);
        float sdev = sqrtf(var);
        u32 ka, kb2;
        tf2x32(0u, 1234u, 0u, 0u, ka, kb2);   // ku
        u32 u0, u1;
        tf2x32(ka, kb2, 0u, 0u, u0, u1);
        u32 bits = u0 ^ u1;
        float u01 = __uint_as_float((bits >> 9) | 0x3f800000u) - 1.0f;
        float uu = fmaxf(1.0f, u01 + 1.0f);
        g_na1 = sdev * uu;
        g_nm1 = nm;
        g_cnt1 = 0u;
    }
}

// ----------------------------- K3: BN1+noise+ReLU -> GEMM2 + N2 gen -------
__global__ void __launch_bounds__(128) k3_mid(const float* __restrict__ w2,
                                              const float* __restrict__ b2,
                                              const float* __restrict__ gamma,
                                              const float* __restrict__ beta) {
    __shared__ float ys[128 * 49];
    __shared__ float ns[128 * 49];
    __shared__ float w2s[F2 * F1];
    __shared__ float b2s[F2];
    __shared__ float sc1[F1], sh1[F1];
    __shared__ float wrs[4 * F2], wrq[4 * F2];
    int tid = threadIdx.x;
    int rowBase = blockIdx.x * 128;

    for (int i = tid; i < F2 * F1; i += 128) w2s[i] = w2[i];
    if (tid < F2) b2s[tid] = b2[tid];
    if (tid < F1) { sc1[tid] = g_scale1[tid]; sh1[tid] = g_shift1[tid]; }
    {
        const float* yg = g_Y1 + (size_t)rowBase * F1;
        const float* ng = g_N1 + (size_t)rowBase * F1;
        for (int i = tid; i < 128 * F1; i += 128) {
            int r = i / F1, c = i - r * F1;
            ys[r * 49 + c] = yg[i];
            ns[r * 49 + c] = ng[i];
        }
    }
    __syncthreads();

    float na = g_na1, nm = g_nm1;
    u32 kn0, kn1;
    tf2x32(0u, 5678u, 0u, 1u, kn0, kn1);     // constant-foldable
    u32 nb2 = (u32)(rowBase + tid) * 24u;

    float acc[F2];
    float n2v[F2];
#pragma unroll
    for (int j = 0; j < F2; j++) acc[j] = b2s[j];

#pragma unroll 4
    for (int c = 0; c < F1; c++) {
        float h   = fmaf(ys[tid * 49 + c], sc1[c], sh1[c]);
        float noi = fmaf(na, ns[tid * 49 + c], nm);
        float zc  = fmaxf(h + noi, 0.f);
#pragma unroll
        for (int j = 0; j < F2; j++)
            acc[j] = fmaf(zc, w2s[j * F1 + c], acc[j]);
        if (c < F2) {                        // generate layer-2 normal
            u32 q0, q1;
            tf2x32(kn0, kn1, 0u, nb2 + (u32)c, q0, q1);
            n2v[c] = jax_normal(q0 ^ q1);
        }
    }

    int lane = tid & 31, wrp = tid >> 5;
#pragma unroll
    for (int j = 0; j < F2; j++) {
        float sv = acc[j], qv = acc[j] * acc[j];
#pragma unroll
        for (int off = 16; off > 0; off >>= 1) {
            sv += __shfl_down_sync(0xffffffffu, sv, off);
            qv += __shfl_down_sync(0xffffffffu, qv, off);
        }
        if (lane == 0) { wrs[wrp * F2 + j] = sv; wrq[wrp * F2 + j] = qv; }
    }

    __syncthreads();
    if (tid < F2) {                          // transposed partials [col][block]
        g_p2s[tid * 512 + blockIdx.x] =
            wrs[tid] + wrs[F2 + tid] + wrs[2 * F2 + tid] + wrs[3 * F2 + tid];
        g_p2q[tid * 512 + blockIdx.x] =
            wrq[tid] + wrq[F2 + tid] + wrq[2 * F2 + tid] + wrq[3 * F2 + tid];
    }

    // staged coalesced writes: Y2 then N2 (reuse ys)
#pragma unroll
    for (int j = 0; j < F2; j++) ys[tid * 25 + j] = acc[j];
    __syncthreads();
    {
        float* yg2 = g_Y2 + (size_t)rowBase * F2;
        for (int i = tid; i < 128 * F2; i += 128) {
            int r = i / F2, j = i - r * F2;
            yg2[i] = ys[r * 25 + j];
        }
    }
    __syncthreads();
#pragma unroll
    for (int j = 0; j < F2; j++) ys[tid * 25 + j] = n2v[j];
    __syncthreads();
    {
        float* ng2 = g_N2 + (size_t)rowBase * F2;
        for (int i = tid; i < 128 * F2; i += 128) {
            int r = i / F2, j = i - r * F2;
            ng2[i] = ys[r * 25 + j];
        }
    }

    // ---- last-block finalize (layer-2 stats + noise consts) ----
    __shared__ u32 fin_last;
    __shared__ float fin_term[F2], fin_beta[F2];
    __threadfence();
    __syncthreads();
    if (tid == 0) fin_last = (atomicAdd(&g_cnt2, 1u) == 511u) ? 1u : 0u;
    __syncthreads();
    if (fin_last == 0u) return;
    __threadfence();

    if (tid < F2) {
        const float4* ps = (const float4*)(g_p2s + (size_t)tid * 512);
        const float4* pq = (const float4*)(g_p2q + (size_t)tid * 512);
        float s = 0.f, q = 0.f;
#pragma unroll 8
        for (int i = 0; i < 128; i++) {
            float4 a = ps[i]; s += (a.x + a.y) + (a.z + a.w);
            float4 b = pq[i]; q += (b.x + b.y) + (b.z + b.w);
        }
        float m = s / 65536.0f;
        float v = fmaxf(q / 65536.0f - m * m, 0.f);
        float ga = gamma[tid], be = beta[tid];
        float sc = ga * rsqrtf(v + EPSBN);
        g_scale2[tid] = sc;
        g_shift2[tid] = be - m * sc;
        fin_beta[tid] = be;
        fin_term[tid] = ga * ga * (v / (v + EPSBN));
    }
    __syncthreads();
    if (tid == 0) {
        float nb = 0.f;
        for (int c = 0; c < F2; c++) nb += fin_beta[c];
        float nm2 = nb / (float)F2;
        float S = 0.f;
        for (int c = 0; c < F2; c++) {
            float d = fin_beta[c] - nm2;
            S += fin_term[c] + d * d;
        }
        float var = (65536.0f * S) / (65536.0f * (float)F2 - 1.0f);
        float sdev = sqrtf(var);
        u32 ka2, kb2;
        tf2x32(0u, 5678u, 0u, 0u, ka2, kb2);  // ku
        u32 u0, u1;
        tf2x32(ka2, kb2, 0u, 0u, u0, u1);
        u32 bits = u0 ^ u1;
        float u01 = __uint_as_float((bits >> 9) | 0x3f800000u) - 1.0f;
        float uu = fmaxf(1.0f, u01 + 1.0f);
        g_na2 = sdev * uu;
        g_nm2 = nm2;
        g_cnt2 = 0u;
    }
}

// ----------------------------- K5: BN2+noise+ReLU -> GEMM3 -> out ---------
__global__ void __launch_bounds__(128) k5_out(const float* __restrict__ w3,
                                              const float* __restrict__ b3,
                                              float* __restrict__ out) {
    __shared__ float ys[128 * 25];
    __shared__ float ns[128 * 25];
    __shared__ float w3s[F3 * F2];
    __shared__ float b3s[F3];
    __shared__ float sc2[F2], sh2[F2];
    int tid = threadIdx.x;
    int rowBase = blockIdx.x * 128;

    for (int i = tid; i < F3 * F2; i += 128) w3s[i] = w3[i];
    if (tid < F3) b3s[tid] = b3[tid];
    if (tid < F2) { sc2[tid] = g_scale2[tid]; sh2[tid] = g_shift2[tid]; }
    {
        const float* yg = g_Y2 + (size_t)rowBase * F2;
        const float* ng = g_N2 + (size_t)rowBase * F2;
        for (int i = tid; i < 128 * F2; i += 128) {
            int r = i / F2, c = i - r * F2;
            ys[r * 25 + c] = yg[i];
            ns[r * 25 + c] = ng[i];
        }
    }
    __syncthreads();

    float na = g_na2, nm = g_nm2;

    float acc[F3];
#pragma unroll
    for (int j = 0; j < F3; j++) acc[j] = b3s[j];

#pragma unroll
    for (int c = 0; c < F2; c++) {
        float h   = fmaf(ys[tid * 25 + c], sc2[c], sh2[c]);
        float noi = fmaf(na, ns[tid * 25 + c], nm);
        float zc  = fmaxf(h + noi, 0.f);
#pragma unroll
        for (int j = 0; j < F3; j++)
            acc[j] = fmaf(zc, w3s[j * F2 + c], acc[j]);
    }

    __syncthreads();
#pragma unroll
    for (int j = 0; j < F3; j++) ys[tid * 11 + j] = acc[j];
    __syncthreads();
    {
        float* og = out + (size_t)rowBase * F3;
        for (int i = tid; i < 128 * F3; i += 128) {
            int r = i / F3, j = i - r * F3;
            og[i] = ys[r * 11 + j];
        }
    }
}

// ----------------------------- launch --------------------------------------
extern "C" void kernel_launch(void* const* d_in, const int* in_sizes, int n_in,
                              void* d_out, int out_size) {
    const float* x      = (const float*)d_in[0];
    const float* w1     = (const float*)d_in[1];
    const float* b1     = (const float*)d_in[2];
    const float* gamma1 = (const float*)d_in[3];
    const float* beta1  = (const float*)d_in[4];
    const float* w2     = (const float*)d_in[5];
    const float* b2     = (const float*)d_in[6];
    const float* gamma2 = (const float*)d_in[7];
    const float* beta2  = (const float*)d_in[8];
    const float* w3     = (const float*)d_in[9];
    const float* b3     = (const float*)d_in[10];
    float* out = (float*)d_out;

    k0_pack<<<74, 128>>>(w1);
    k1_mma<<<512, 128>>>(x, b1, gamma1, beta1);
    k3_mid<<<512, 128>>>(w2, b2, gamma2, beta2);
    k5_out<<<512, 128>>>(w3, b3, out);
}

// round 13
// speedup vs baseline: 1.4217x; 1.4217x over previous
#include <cuda_runtime.h>
#include <cuda_fp16.h>
#include <cstddef>
#include <cstdint>

typedef unsigned int u32;
typedef unsigned long long ull;

#define NROWS 65536
#define F1 48
#define F2 24
#define F3 10
#define KDIM 784
#define EPSBN 1e-5f

// ----------------------------- device scratch -----------------------------
__device__ float g_Y1[(size_t)NROWS * F1];
__device__ uint4 g_w1p[F1 * 49 * 4];      // packed split-fp16 w1 fragments
__device__ float g_p1s[F1 * 512];
__device__ float g_p1q[F1 * 512];
__device__ float g_p2s[F2 * 512];
__device__ float g_p2q[F2 * 512];
__device__ float g_scale1[F1], g_shift1[F1];
__device__ float g_scale2[F2], g_shift2[F2];
__device__ float g_na1, g_nm1, g_na2, g_nm2;
__device__ u32   g_k1a, g_k1b;
__device__ u32   g_cnt1 = 0, g_cnt2 = 0;
__device__ u32   g_epoch2 = 0;            // grid-barrier epoch (monotonic)

// ----------------------------- helpers ------------------------------------
__device__ __forceinline__ u32 pk2(float a, float b) {
    u32 h;
    asm("cvt.rn.f16x2.f32 %0, %1, %2;" : "=r"(h) : "f"(b), "f"(a));
    return h;
}
__device__ __forceinline__ void split2(float a, float b, u32 &hi, u32 &lo) {
    asm("cvt.rn.f16x2.f32 %0, %1, %2;" : "=r"(hi) : "f"(b), "f"(a));
    float f0, f1;
    asm("{.reg .f16 x,y; mov.b32 {x,y}, %2; cvt.f32.f16 %0, x; cvt.f32.f16 %1, y;}"
        : "=f"(f0), "=f"(f1) : "r"(hi));
    asm("cvt.rn.f16x2.f32 %0, %1, %2;" : "=r"(lo) : "f"(b - f1), "f"(a - f0));
}

#define MMA_F16(c, a, b0v, b1v) \
    asm volatile("mma.sync.aligned.m16n8k16.row.col.f32.f16.f16.f32 " \
        "{%0,%1,%2,%3}, {%4,%5,%6,%7}, {%8,%9}, {%0,%1,%2,%3};" \
        : "+f"((c)[0]), "+f"((c)[1]), "+f"((c)[2]), "+f"((c)[3]) \
        : "r"((a)[0]), "r"((a)[1]), "r"((a)[2]), "r"((a)[3]), \
          "r"(b0v), "r"(b1v))

// ----------------------------- PRNG ----------------------------------------
__device__ __forceinline__ void tf2x32(u32 k0, u32 k1, u32 x0, u32 x1,
                                       u32 &o0, u32 &o1) {
    u32 k2 = k0 ^ k1 ^ 0x1BD11BDAu;
    x0 += k0; x1 += k1;
#define TF_R(r) { x0 += x1; x1 = __funnelshift_l(x1, x1, (r)); x1 ^= x0; }
    TF_R(13) TF_R(15) TF_R(26) TF_R(6)   x0 += k1; x1 += k2 + 1u;
    TF_R(17) TF_R(29) TF_R(16) TF_R(24)  x0 += k2; x1 += k0 + 2u;
    TF_R(13) TF_R(15) TF_R(26) TF_R(6)   x0 += k0; x1 += k1 + 3u;
    TF_R(17) TF_R(29) TF_R(16) TF_R(24)  x0 += k1; x1 += k2 + 4u;
    TF_R(13) TF_R(15) TF_R(26) TF_R(6)   x0 += k2; x1 += k0 + 5u;
#undef TF_R
    o0 = x0; o1 = x1;
}

__device__ __forceinline__ float jax_normal(u32 bits) {
    float u01 = __uint_as_float((bits >> 9) | 0x3f800000u) - 1.0f;
    float u   = fmaxf(-0.99999994f, fmaf(u01, 2.0f, -0.99999994f));
    float w   = -log1pf(-u * u);
    float p;
    if (w < 5.0f) {
        w -= 2.5f;
        p = 2.81022636e-08f;
        p = fmaf(p, w, 3.43273939e-07f);
        p = fmaf(p, w, -3.5233877e-06f);
        p = fmaf(p, w, -4.39150654e-06f);
        p = fmaf(p, w, 0.00021858087f);
        p = fmaf(p, w, -0.00125372503f);
        p = fmaf(p, w, -0.00417768164f);
        p = fmaf(p, w, 0.246640727f);
        p = fmaf(p, w, 1.50140941f);
    } else {
        w = sqrtf(w) - 3.0f;
        p = -0.000200214257f;
        p = fmaf(p, w, 0.000100950558f);
        p = fmaf(p, w, 0.00134934322f);
        p = fmaf(p, w, -0.00367342844f);
        p = fmaf(p, w, 0.00573950773f);
        p = fmaf(p, w, -0.0076224613f);
        p = fmaf(p, w, 0.00943887047f);
        p = fmaf(p, w, 1.00167406f);
        p = fmaf(p, w, 2.83297682f);
    }
    return 1.41421356f * (p * u);
}

// ----------------------------- K0: pack w1 fragments (k-permuted) ---------
__global__ void __launch_bounds__(128) k0_pack(const float* __restrict__ w1) {
    int e = blockIdx.x * 128 + threadIdx.x;
    if (e >= F1 * 49 * 4) return;
    int t = e & 3;
    int ks = (e >> 2) % 49;
    int r = e / 196;
    float4 v = *(const float4*)(w1 + (size_t)r * KDIM + ks * 16 + t * 4);
    u32 h0, l0, h1, l1;
    split2(v.x, v.y, h0, l0);
    split2(v.z, v.w, h1, l1);
    g_w1p[e] = make_uint4(h0, h1, l0, l1);
}

// ----------------------------- K1: streaming HMMA GEMM (R11, unchanged) ---
__global__ void __launch_bounds__(128, 4)
k1_mma(const float* __restrict__ x, const float* __restrict__ b1,
       const float* __restrict__ gamma, const float* __restrict__ beta) {
    __shared__ float ys[128 * 49];
    __shared__ float bsm[F1];
    int tid = threadIdx.x;
    int lane = tid & 31, wrp = tid >> 5;
    int g = lane >> 2, t = lane & 3;
    int rowBase = blockIdx.x * 128;

    if (tid < F1) bsm[tid] = b1[tid];

    const float* xA = x + (size_t)(rowBase + wrp * 32 + g) * KDIM + t * 4;
    const uint4* wp = g_w1p + g * 196 + t;    // + nt*1568 + ks*4

    float C[2][6][4];
#pragma unroll
    for (int mt = 0; mt < 2; mt++)
#pragma unroll
        for (int nt = 0; nt < 6; nt++)
#pragma unroll
            for (int e = 0; e < 4; e++) C[mt][nt][e] = 0.f;

    float4 e0, e1, e2, e3, o0, o1, o2, o3;
#define LDA(ks, v0, v1, v2, v3) { \
    const float* p_ = xA + (ks) * 16; \
    v0 = __ldcs((const float4*)p_); \
    v1 = __ldcs((const float4*)(p_ + 8 * KDIM)); \
    v2 = __ldcs((const float4*)(p_ + 16 * KDIM)); \
    v3 = __ldcs((const float4*)(p_ + 24 * KDIM)); }

#define CVT(v0, v1, v2, v3, a0, a1) { \
    a0[0] = pk2(v0.x, v0.y); a0[1] = pk2(v1.x, v1.y); \
    a0[2] = pk2(v0.z, v0.w); a0[3] = pk2(v1.z, v1.w); \
    a1[0] = pk2(v2.x, v2.y); a1[1] = pk2(v3.x, v3.y); \
    a1[2] = pk2(v2.z, v2.w); a1[3] = pk2(v3.z, v3.w); }

#define MMASTEP(ks, a0, a1) { \
    _Pragma("unroll") \
    for (int nt = 0; nt < 6; nt++) { \
        uint4 w = __ldg(wp + nt * 1568 + (ks) * 4); \
        MMA_F16(C[0][nt], a0, w.x, w.y); \
        MMA_F16(C[1][nt], a1, w.x, w.y); \
        MMA_F16(C[0][nt], a0, w.z, w.w); \
        MMA_F16(C[1][nt], a1, w.z, w.w); } }

    LDA(0, e0, e1, e2, e3)
    LDA(1, o0, o1, o2, o3)

#pragma unroll 1
    for (int ks = 0; ks < 48; ks += 2) {
        u32 a0[4], a1[4];
        CVT(e0, e1, e2, e3, a0, a1)
        LDA(ks + 2, e0, e1, e2, e3)
        MMASTEP(ks, a0, a1)
        CVT(o0, o1, o2, o3, a0, a1)
        if (ks + 3 < 49) { LDA(ks + 3, o0, o1, o2, o3) }
        MMASTEP(ks + 1, a0, a1)
    }
    {
        u32 a0[4], a1[4];
        CVT(e0, e1, e2, e3, a0, a1)
        MMASTEP(48, a0, a1)
    }
#undef LDA
#undef CVT
#undef MMASTEP

    int rg = lane >> 2, cg = (lane & 3) * 2;
#pragma unroll
    for (int mt = 0; mt < 2; mt++) {
        int r0 = wrp * 32 + mt * 16 + rg;
#pragma unroll
        for (int nt = 0; nt < 6; nt++) {
            int col = nt * 8 + cg;
            ys[r0 * 49 + col]           = C[mt][nt][0] + bsm[col];
            ys[r0 * 49 + col + 1]       = C[mt][nt][1] + bsm[col + 1];
            ys[(r0 + 8) * 49 + col]     = C[mt][nt][2] + bsm[col];
            ys[(r0 + 8) * 49 + col + 1] = C[mt][nt][3] + bsm[col + 1];
        }
    }
    __syncthreads();

    if (tid < F1) {
        float s = 0.f, q = 0.f;
        for (int r = 0; r < 128; r++) {
            float v = ys[r * 49 + tid];
            s += v; q += v * v;
        }
        g_p1s[tid * 512 + blockIdx.x] = s;
        g_p1q[tid * 512 + blockIdx.x] = q;
    }
    float* yg = g_Y1 + (size_t)rowBase * F1;
#pragma unroll 4
    for (int p = 0; p < 48; p++) {
        int i = p * 128 + tid;
        int r = i / F1, cc = i - r * F1;
        yg[i] = ys[r * 49 + cc];
    }

    __shared__ u32 fin_last;
    __shared__ float fin_term[F1], fin_beta[F1];
    __threadfence();
    __syncthreads();
    if (tid == 0) fin_last = (atomicAdd(&g_cnt1, 1u) == 511u) ? 1u : 0u;
    __syncthreads();
    if (fin_last == 0u) return;
    __threadfence();

    if (tid < F1) {
        const float4* ps = (const float4*)(g_p1s + (size_t)tid * 512);
        const float4* pq = (const float4*)(g_p1q + (size_t)tid * 512);
        float s = 0.f, q = 0.f;
#pragma unroll 8
        for (int i = 0; i < 128; i++) {
            float4 a = ps[i]; s += (a.x + a.y) + (a.z + a.w);
            float4 b = pq[i]; q += (b.x + b.y) + (b.z + b.w);
        }
        float m = s / 65536.0f;
        float v = fmaxf(q / 65536.0f - m * m, 0.f);
        float ga = gamma[tid], be = beta[tid];
        float sc = ga * rsqrtf(v + EPSBN);
        g_scale1[tid] = sc;
        g_shift1[tid] = be - m * sc;
        fin_beta[tid] = be;
        fin_term[tid] = ga * ga * (v / (v + EPSBN));
    }
    __syncthreads();
    if (tid == 0) {
        float nb = 0.f;
        for (int c = 0; c < F1; c++) nb += fin_beta[c];
        float nm = nb / (float)F1;
        float S = 0.f;
        for (int c = 0; c < F1; c++) {
            float d = fin_beta[c] - nm;
            S += fin_term[c] + d * d;
        }
        float var = (65536.0f * S) / (65536.0f * (float)F1 - 1.0f);
        float sdev = sqrtf(var);
        u32 ka, kb2, na, nbk;
        tf2x32(0u, 1234u, 0u, 0u, ka, kb2);
        tf2x32(0u, 1234u, 0u, 1u, na, nbk);
        u32 u0, u1;
        tf2x32(ka, kb2, 0u, 0u, u0, u1);
        u32 bits = u0 ^ u1;
        float u01 = __uint_as_float((bits >> 9) | 0x3f800000u) - 1.0f;
        float uu = fmaxf(1.0f, u01 + 1.0f);
        g_na1 = sdev * uu;
        g_nm1 = nm;
        g_k1a = na; g_k1b = nbk;
        g_cnt1 = 0u;
    }
}

// ------------- K35: BN1+noise1+GEMM2 -> grid sync -> BN2+noise2+GEMM3 -----
// Single wave (512 CTAs, 4/SM) with epoch-based software grid barrier.
__global__ void __launch_bounds__(128, 4)
k35_fused(const float* __restrict__ w2, const float* __restrict__ b2,
          const float* __restrict__ gamma2, const float* __restrict__ beta2,
          const float* __restrict__ w3, const float* __restrict__ b3,
          float* __restrict__ out) {
    __shared__ float ys[128 * 49];
    __shared__ float w2s[F2 * F1];
    __shared__ float w3s[F3 * F2];
    __shared__ float b2s[F2], b3s[F3];
    __shared__ float sc1[F1], sh1[F1];
    __shared__ float sc2s[F2], sh2s[F2];
    __shared__ float wrs[4 * F2], wrq[4 * F2];
    __shared__ u32 sh_epoch;
    __shared__ float sh_na2, sh_nm2;
    int tid = threadIdx.x;
    int rowBase = blockIdx.x * 128;

    if (tid == 0) sh_epoch = *(volatile u32*)&g_epoch2;   // snapshot BEFORE arrival

    for (int i = tid; i < F2 * F1; i += 128) w2s[i] = w2[i];
    for (int i = tid; i < F3 * F2; i += 128) w3s[i] = w3[i];
    if (tid < F2) b2s[tid] = b2[tid];
    if (tid < F3) b3s[tid] = b3[tid];
    if (tid < F1) { sc1[tid] = g_scale1[tid]; sh1[tid] = g_shift1[tid]; }
    {
        const float* yg = g_Y1 + (size_t)rowBase * F1;
        for (int i = tid; i < 128 * F1; i += 128) {
            int r = i / F1, c = i - r * F1;
            ys[r * 49 + c] = yg[i];
        }
    }
    __syncthreads();

    float na = g_na1, nm = g_nm1;
    u32 ka = g_k1a, kb = g_k1b;
    u32 base = (u32)(rowBase + tid) * (u32)F1;

    float acc[F2];
#pragma unroll
    for (int j = 0; j < F2; j++) acc[j] = b2s[j];

#pragma unroll 4
    for (int c = 0; c < F1; c++) {
        float h = fmaf(ys[tid * 49 + c], sc1[c], sh1[c]);
        u32 o0, o1;
        tf2x32(ka, kb, 0u, base + (u32)c, o0, o1);
        float noi = fmaf(na, jax_normal(o0 ^ o1), nm);
        float zc = fmaxf(h + noi, 0.f);
#pragma unroll
        for (int j = 0; j < F2; j++)
            acc[j] = fmaf(zc, w2s[j * F1 + c], acc[j]);
    }

    // ---- block stats partials ----
    int lane = tid & 31, wrp = tid >> 5;
#pragma unroll
    for (int j = 0; j < F2; j++) {
        float sv = acc[j], qv = acc[j] * acc[j];
#pragma unroll
        for (int off = 16; off > 0; off >>= 1) {
            sv += __shfl_down_sync(0xffffffffu, sv, off);
            qv += __shfl_down_sync(0xffffffffu, qv, off);
        }
        if (lane == 0) { wrs[wrp * F2 + j] = sv; wrq[wrp * F2 + j] = qv; }
    }
    __syncthreads();
    if (tid < F2) {
        g_p2s[tid * 512 + blockIdx.x] =
            wrs[tid] + wrs[F2 + tid] + wrs[2 * F2 + tid] + wrs[3 * F2 + tid];
        g_p2q[tid * 512 + blockIdx.x] =
            wrq[tid] + wrq[F2 + tid] + wrq[2 * F2 + tid] + wrq[3 * F2 + tid];
    }

    // ---- arrive ----
    __shared__ u32 fin_last;
    __threadfence();
    __syncthreads();
    if (tid == 0) fin_last = (atomicAdd(&g_cnt2, 1u) == 511u) ? 1u : 0u;
    __syncthreads();

    // ---- generate layer-2 normals while other blocks finish ----
    float n2v[F2];
    {
        u32 kn0, kn1;
        tf2x32(0u, 5678u, 0u, 1u, kn0, kn1);   // compile-time foldable
        u32 nb2 = (u32)(rowBase + tid) * (u32)F2;
#pragma unroll 4
        for (int c = 0; c < F2; c++) {
            u32 q0, q1;
            tf2x32(kn0, kn1, 0u, nb2 + (u32)c, q0, q1);
            n2v[c] = jax_normal(q0 ^ q1);
        }
    }

    // ---- last block: finalize layer-2 stats, bump epoch ----
    if (fin_last) {
        __shared__ float fin_term[F2], fin_beta[F2];
        __threadfence();
        if (tid < F2) {
            const float4* ps = (const float4*)(g_p2s + (size_t)tid * 512);
            const float4* pq = (const float4*)(g_p2q + (size_t)tid * 512);
            float s = 0.f, q = 0.f;
#pragma unroll 8
            for (int i = 0; i < 128; i++) {
                float4 a = ps[i]; s += (a.x + a.y) + (a.z + a.w);
                float4 b = pq[i]; q += (b.x + b.y) + (b.z + b.w);
            }
            float m = s / 65536.0f;
            float v = fmaxf(q / 65536.0f - m * m, 0.f);
            float ga = gamma2[tid], be = beta2[tid];
            float sc = ga * rsqrtf(v + EPSBN);
            g_scale2[tid] = sc;
            g_shift2[tid] = be - m * sc;
            fin_beta[tid] = be;
            fin_term[tid] = ga * ga * (v / (v + EPSBN));
        }
        __syncthreads();
        if (tid == 0) {
            float nb = 0.f;
            for (int c = 0; c < F2; c++) nb += fin_beta[c];
            float nm2 = nb / (float)F2;
            float S = 0.f;
            for (int c = 0; c < F2; c++) {
                float d = fin_beta[c] - nm2;
                S += fin_term[c] + d * d;
            }
            float var = (65536.0f * S) / (65536.0f * (float)F2 - 1.0f);
            float sdev = sqrtf(var);
            u32 ka2, kb2, u0, u1;
            tf2x32(0u, 5678u, 0u, 0u, ka2, kb2);
            tf2x32(ka2, kb2, 0u, 0u, u0, u1);
            u32 bits = u0 ^ u1;
            float u01 = __uint_as_float((bits >> 9) | 0x3f800000u) - 1.0f;
            float uu = fmaxf(1.0f, u01 + 1.0f);
            g_na2 = sdev * uu;
            g_nm2 = nm2;
            g_cnt2 = 0u;
            __threadfence();
            atomicAdd(&g_epoch2, 1u);         // release
        }
    }

    // ---- grid barrier: spin until epoch advances ----
    if (tid == 0) {
        u32 e0 = sh_epoch;
        while (*(volatile u32*)&g_epoch2 == e0) { __nanosleep(64); }
    }
    __syncthreads();
    __threadfence();                          // acquire

    if (tid < F2) { sc2s[tid] = g_scale2[tid]; sh2s[tid] = g_shift2[tid]; }
    if (tid == 0) { sh_na2 = g_na2; sh_nm2 = g_nm2; }
    __syncthreads();

    // ---- BN2 + noise2 + ReLU + GEMM3 (all register-resident) ----
    float na2 = sh_na2, nm2 = sh_nm2;
    float acc3[F3];
#pragma unroll
    for (int j = 0; j < F3; j++) acc3[j] = b3s[j];
#pragma unroll
    for (int c = 0; c < F2; c++) {
        float h   = fmaf(acc[c], sc2s[c], sh2s[c]);
        float noi = fmaf(na2, n2v[c], nm2);
        float zc  = fmaxf(h + noi, 0.f);
#pragma unroll
        for (int j = 0; j < F3; j++)
            acc3[j] = fmaf(zc, w3s[j * F2 + c], acc3[j]);
    }

    __syncthreads();
#pragma unroll
    for (int j = 0; j < F3; j++) ys[tid * 11 + j] = acc3[j];
    __syncthreads();
    {
        float* og = out + (size_t)rowBase * F3;
        for (int i = tid; i < 128 * F3; i += 128) {
            int r = i / F3, j = i - r * F3;
            og[i] = ys[r * 11 + j];
        }
    }
}

// ----------------------------- launch --------------------------------------
extern "C" void kernel_launch(void* const* d_in, const int* in_sizes, int n_in,
                              void* d_out, int out_size) {
    const float* x      = (const float*)d_in[0];
    const float* w1     = (const float*)d_in[1];
    const float* b1     = (const float*)d_in[2];
    const float* gamma1 = (const float*)d_in[3];
    const float* beta1  = (const float*)d_in[4];
    const float* w2     = (const float*)d_in[5];
    const float* b2     = (const float*)d_in[6];
    const float* gamma2 = (const float*)d_in[7];
    const float* beta2  = (const float*)d_in[8];
    const float* w3     = (const float*)d_in[9];
    const float* b3     = (const float*)d_in[10];
    float* out = (float*)d_out;

    k0_pack<<<74, 128>>>(w1);
    k1_mma<<<512, 128>>>(x, b1, gamma1, beta1);
    k35_fused<<<512, 128>>>(w2, b2, gamma2, beta2, w3, b3, out);
}